// round 5
// baseline (speedup 1.0000x reference)
#include <cuda_runtime.h>
#include <math.h>
#include <stdint.h>

#define HW   (128 * 128)
#define Hh   128
#define Ww   128
#define Bb   4
#define Cc   64
#define Oo   64

// Scratch: offsets/mask planes [B][27][H][W]  (0..8 dy_k, 9..17 dx_k, 18..26 mask_k)
__device__ float g_scratch[Bb * 27 * HW];
// Pre-transposed offset+mod weights: [k][c][28]  (0..17 offset-out, 18..26 mod-out, 27 pad)
__device__ float g_wt2[9 * 64 * 28];
// Pre-split tf32 B matrices: [tap][o][pos(c)] with interleaved c layout so the
// (b0,b1) MMA fragment pair is one LDS.64:  pos(c) = (c>>3)*8 + (c&3)*2 + ((c>>2)&1)
__device__ float g_wbh[9 * 64 * 64];
__device__ float g_wbl[9 * 64 * 64];

typedef unsigned long long ull;

// ---------------- helpers ----------------
__device__ __forceinline__ uint32_t f2tf32(float s) {
    uint32_t r; asm("cvt.rna.tf32.f32 %0, %1;" : "=r"(r) : "f"(s)); return r;
}
__device__ __forceinline__ void ffma2(ull &acc, ull a, ull b) {
    asm("fma.rn.f32x2 %0, %1, %2, %0;" : "+l"(acc) : "l"(a), "l"(b));
}
__device__ __forceinline__ ull pack2(float x, float y) {
    ull r; asm("mov.b64 %0, {%1, %2};" : "=l"(r) : "f"(x), "f"(y)); return r;
}
__device__ __forceinline__ void unpack2(ull v, float &x, float &y) {
    asm("mov.b64 {%0, %1}, %2;" : "=f"(x), "=f"(y) : "l"(v));
}

#define MMA_TF32(d, a, b0, b1) \
    asm volatile("mma.sync.aligned.m16n8k8.row.col.f32.tf32.tf32.f32 " \
        "{%0,%1,%2,%3}, {%4,%5,%6,%7}, {%8,%9}, {%0,%1,%2,%3};" \
        : "+f"((d)[0]), "+f"((d)[1]), "+f"((d)[2]), "+f"((d)[3]) \
        : "r"((a)[0]), "r"((a)[1]), "r"((a)[2]), "r"((a)[3]), "r"(b0), "r"(b1))

// ---------------------------------------------------------------------------
// Prep: pre-transposed offmask weights + tf32-split interleaved B matrices.
// ---------------------------------------------------------------------------
__global__ void prep_kernel(const float* __restrict__ w,
                            const float* __restrict__ ow,
                            const float* __restrict__ mw)
{
    int i = blockIdx.x * 256 + threadIdx.x;
    if (i < 9 * 4096) {
        int k = i >> 12;      // tap
        int r = i & 4095;
        int o = r >> 6;       // out channel
        int c = r & 63;       // in channel (K index)
        float v = w[o * 576 + c * 9 + k];
        uint32_t hb = f2tf32(v);
        float hif = __uint_as_float(hb);
        int pos = ((c >> 3) << 3) + ((c & 3) << 1) + ((c >> 2) & 1);
        g_wbh[k * 4096 + o * 64 + pos] = hif;
        g_wbl[k * 4096 + o * 64 + pos] = __uint_as_float(f2tf32(v - hif));
    }
    int j = i - 9 * 4096;
    if (j >= 0 && j < 9 * 64 * 28) {
        int k = j / (64 * 28);
        int r = j % (64 * 28);
        int c = r / 28;
        int t = r % 28;
        float v = 0.f;
        if (t < 18)      v = ow[t * 576 + c * 9 + k];
        else if (t < 27) v = mw[(t - 18) * 576 + c * 9 + k];
        g_wt2[j] = v;
    }
}

// ---------------------------------------------------------------------------
// Kernel 1: fused offset-conv (18) + mod-conv (9) + 2*sigmoid. (unchanged)
// ---------------------------------------------------------------------------
__global__ __launch_bounds__(128, 8)
void offmask_kernel(const float* __restrict__ omap, const float* __restrict__ mmap,
                    const float* __restrict__ obias, const float* __restrict__ mbias)
{
    __shared__ float ws[64 * 28];

    const int tid = threadIdx.x;
    const int b   = blockIdx.x >> 7;
    const int row = blockIdx.x & 127;
    const int wo  = tid;

    ull acc[14];
#pragma unroll
    for (int i = 0; i < 14; i++) acc[i] = 0ull;

    const float* ob = omap + (size_t)b * Cc * HW;
    const float* mb = mmap + (size_t)b * Cc * HW;

    for (int k = 0; k < 9; k++) {
        __syncthreads();
        for (int i = tid; i < 64 * 28; i += 128) ws[i] = g_wt2[k * 64 * 28 + i];
        __syncthreads();

        const int ki = k / 3, kj = k % 3;
        const int py = row - 1 + ki;
        const int px = wo - 1 + kj;
        const bool valid = ((unsigned)py < (unsigned)Hh) & ((unsigned)px < (unsigned)Ww);
        const float* qo = ob + py * Ww + px;
        const float* qm = mb + py * Ww + px;

#pragma unroll 4
        for (int c = 0; c < Cc; c++) {
            float iv = valid ? __ldg(qo + c * HW) : 0.f;
            float mv = valid ? __ldg(qm + c * HW) : 0.f;
            ull ai = pack2(iv, iv);
            ull am = pack2(mv, mv);
            const ulonglong2* wc = (const ulonglong2*)&ws[c * 28];
            ulonglong2 w;
            w = wc[0]; ffma2(acc[0],  ai, w.x); ffma2(acc[1],  ai, w.y);
            w = wc[1]; ffma2(acc[2],  ai, w.x); ffma2(acc[3],  ai, w.y);
            w = wc[2]; ffma2(acc[4],  ai, w.x); ffma2(acc[5],  ai, w.y);
            w = wc[3]; ffma2(acc[6],  ai, w.x); ffma2(acc[7],  ai, w.y);
            w = wc[4]; ffma2(acc[8],  ai, w.x); ffma2(acc[9],  am, w.y);
            w = wc[5]; ffma2(acc[10], am, w.x); ffma2(acc[11], am, w.y);
            w = wc[6]; ffma2(acc[12], am, w.x); ffma2(acc[13], am, w.y);
        }
    }

    float v[28];
#pragma unroll
    for (int i = 0; i < 14; i++) unpack2(acc[i], v[2 * i], v[2 * i + 1]);

    const int p = row * Ww + wo;
    float* S = g_scratch + (size_t)b * 27 * HW;
#pragma unroll
    for (int k = 0; k < 9; k++) {
        S[k * HW + p]       = v[2 * k]     + __ldg(&obias[2 * k]);
        S[(9 + k) * HW + p] = v[2 * k + 1] + __ldg(&obias[2 * k + 1]);
    }
#pragma unroll
    for (int t = 0; t < 9; t++) {
        float z = v[18 + t] + __ldg(&mbias[t]);
        S[(18 + t) * HW + p] = 2.0f / (1.0f + expf(-z));
    }
}

// ---------------------------------------------------------------------------
// Kernel 2: deformable conv, warp-level tf32 MMA implicit GEMM, 256 threads.
// CTA = 1 image row (M=128 pixels), N=64 outch, K=576 (9 taps x 64 ch).
// Sampling: thread (tid>>7) handles 32 channels of pixel (tid&127).
// GEMM: 8 warps, warp w owns m-tile rows [w*16, w*16+16), 8 n-tiles,
// 3-product tf32 precision split. B fragments via LDS.64 (interleaved layout).
// ---------------------------------------------------------------------------
#define SA_STRIDE 68
#define SA_HI 0
#define SA_LO (SA_HI + 128 * SA_STRIDE)          // 8704
#define SB_HI (SA_LO + 128 * SA_STRIDE)          // 17408
#define SB_LO (SB_HI + 64 * SA_STRIDE)           // 21760
#define SM_FLOATS (SB_LO + 64 * SA_STRIDE)       // 26112 floats = 104448 B

__global__ __launch_bounds__(256, 2)
void deform_kernel(const float* __restrict__ x, float* __restrict__ out)
{
    extern __shared__ float smf[];
    uint32_t* smu = (uint32_t*)smf;

    const int tid  = threadIdx.x;
    const int lane = tid & 31;
    const int warp = tid >> 5;
    const int g    = lane >> 2;      // group id 0..7
    const int tg   = lane & 3;       // thread-in-group 0..3

    const int b    = blockIdx.x >> 7;
    const int row  = blockIdx.x & 127;
    const int pix  = tid & 127;      // pixel x = M row index
    const int half = tid >> 7;       // channel half 0/1
    const int p    = row * Ww + pix;

    const float* S  = g_scratch + (size_t)b * 27 * HW;
    const float* xb = x + (size_t)b * Cc * HW + half * 32 * HW;

    float acc[8][4];
#pragma unroll
    for (int nt = 0; nt < 8; nt++)
#pragma unroll
        for (int r = 0; r < 4; r++) acc[nt][r] = 0.f;

#pragma unroll 1
    for (int k = 0; k < 9; k++) {
        __syncthreads();   // previous tap's fragment reads complete

        // ---- stage B tiles (interleaved layout preserved by raw copy) ----
        {
            const float4* sh = (const float4*)&g_wbh[k * 4096];
            const float4* sl = (const float4*)&g_wbl[k * 4096];
#pragma unroll
            for (int i = tid; i < 1024; i += 256) {
                int o = i >> 4, q = i & 15;
                float4 vh = sh[o * 16 + q];
                float4 vl = sl[o * 16 + q];
                *(float4*)&smf[SB_HI + o * SA_STRIDE + q * 4] = vh;
                *(float4*)&smf[SB_LO + o * SA_STRIDE + q * 4] = vl;
            }
        }

        // ---- tap descriptor (per pixel; both halves compute the same) ----
        const float dy = S[k * HW + p];
        const float dx = S[(9 + k) * HW + p];
        const float m  = S[(18 + k) * HW + p];
        const float py = dy + (float)(row - 1 + k / 3);
        const float px = dx + (float)(pix - 1 + k % 3);
        const float fy = floorf(py), fx = floorf(px);
        const int y0 = (int)fy, x0 = (int)fx;
        const int y1 = y0 + 1,  x1 = x0 + 1;
        const float wy = py - fy, wx = px - fx;

        const bool vy0 = ((unsigned)y0 < (unsigned)Hh);
        const bool vy1 = ((unsigned)y1 < (unsigned)Hh);
        const bool vx0 = ((unsigned)x0 < (unsigned)Ww);
        const bool vx1 = ((unsigned)x1 < (unsigned)Ww);
        const int y0c = min(max(y0, 0), Hh - 1);
        const int y1c = min(max(y1, 0), Hh - 1);
        const int x0c = min(max(x0, 0), Ww - 1);
        const int x1c = min(max(x1, 0), Ww - 1);

        float c00 = (1.f - wy) * (1.f - wx) * m; c00 = (vy0 & vx0) ? c00 : 0.f;
        float c01 = (1.f - wy) * wx         * m; c01 = (vy0 & vx1) ? c01 : 0.f;
        float c10 = wy * (1.f - wx)         * m; c10 = (vy1 & vx0) ? c10 : 0.f;
        float c11 = wy * wx                 * m; c11 = (vy1 & vx1) ? c11 : 0.f;

        const float* q00 = xb + y0c * Ww + x0c;
        const float* q01 = xb + y0c * Ww + x1c;
        const float* q10 = xb + y1c * Ww + x0c;
        const float* q11 = xb + y1c * Ww + x1c;

        // ---- sample 32 channels (this half), split hi/lo, STS into A ----
#pragma unroll 4
        for (int cg = 0; cg < 8; cg++) {
            float hi4[4], lo4[4];
#pragma unroll
            for (int j = 0; j < 4; j++) {
                const int c = cg * 4 + j;
                float s = __ldg(q00 + c * HW) * c00;
                s = fmaf(__ldg(q01 + c * HW), c01, s);
                s = fmaf(__ldg(q10 + c * HW), c10, s);
                s = fmaf(__ldg(q11 + c * HW), c11, s);
                uint32_t hb = f2tf32(s);
                hi4[j] = __uint_as_float(hb);
                lo4[j] = __uint_as_float(f2tf32(s - hi4[j]));
            }
            const int cbase = half * 32 + cg * 4;
            *(float4*)&smf[SA_HI + pix * SA_STRIDE + cbase] =
                make_float4(hi4[0], hi4[1], hi4[2], hi4[3]);
            *(float4*)&smf[SA_LO + pix * SA_STRIDE + cbase] =
                make_float4(lo4[0], lo4[1], lo4[2], lo4[3]);
        }

        __syncthreads();

        // ---- GEMM: 8 k-steps x 8 n-tiles x 3 split products (1 m-tile/warp) ----
#pragma unroll
        for (int ks = 0; ks < 8; ks++) {
            uint32_t ah[4], al[4];
            {
                const int r0 = warp * 16 + g;
                const int base = r0 * SA_STRIDE + ks * 8 + tg;
                ah[0] = smu[SA_HI + base];
                ah[1] = smu[SA_HI + base + 8 * SA_STRIDE];
                ah[2] = smu[SA_HI + base + 4];
                ah[3] = smu[SA_HI + base + 8 * SA_STRIDE + 4];
                al[0] = smu[SA_LO + base];
                al[1] = smu[SA_LO + base + 8 * SA_STRIDE];
                al[2] = smu[SA_LO + base + 4];
                al[3] = smu[SA_LO + base + 8 * SA_STRIDE + 4];
            }
#pragma unroll
            for (int nt = 0; nt < 8; nt++) {
                const int o  = nt * 8 + g;
                const int bb = o * SA_STRIDE + ks * 8 + tg * 2;
                uint2 bh = *(const uint2*)&smu[SB_HI + bb];
                uint2 bl = *(const uint2*)&smu[SB_LO + bb];
                MMA_TF32(acc[nt], ah, bh.x, bh.y);
                MMA_TF32(acc[nt], al, bh.x, bh.y);
                MMA_TF32(acc[nt], ah, bl.x, bl.y);
            }
        }
    }

    // ---- epilogue: write D fragments to out[b][o][row][x] ----
    float* ob = out + (size_t)b * Oo * HW + row * Ww;
    {
        const int r0 = warp * 16 + g;    // pixel x for c0,c1
        const int r1 = r0 + 8;           // pixel x for c2,c3
#pragma unroll
        for (int nt = 0; nt < 8; nt++) {
            const int o0 = nt * 8 + tg * 2;
            ob[(o0)     * HW + r0] = acc[nt][0];
            ob[(o0 + 1) * HW + r0] = acc[nt][1];
            ob[(o0)     * HW + r1] = acc[nt][2];
            ob[(o0 + 1) * HW + r1] = acc[nt][3];
        }
    }
}

// ---------------------------------------------------------------------------

extern "C" void kernel_launch(void* const* d_in, const int* in_sizes, int n_in,
                              void* d_out, int out_size)
{
    const float* x     = (const float*)d_in[0];
    const float* omap  = (const float*)d_in[1];
    const float* mmap  = (const float*)d_in[2];
    const float* ow    = (const float*)d_in[3];
    const float* obias = (const float*)d_in[4];
    const float* mw    = (const float*)d_in[5];
    const float* mbias = (const float*)d_in[6];
    const float* w     = (const float*)d_in[7];
    float* out = (float*)d_out;

    const int prep_total = 9 * 4096 + 9 * 64 * 28;
    prep_kernel<<<(prep_total + 255) / 256, 256>>>(w, ow, mw);

    dim3 grid(Bb * Hh);     // 512 blocks, 1 image row each
    offmask_kernel<<<grid, 128>>>(omap, mmap, obias, mbias);

    const int smem_bytes = SM_FLOATS * (int)sizeof(float);   // 104448
    cudaFuncSetAttribute(deform_kernel, cudaFuncAttributeMaxDynamicSharedMemorySize, smem_bytes);
    deform_kernel<<<grid, 256, smem_bytes>>>(x, out);
}